// round 10
// baseline (speedup 1.0000x reference)
#include <cuda_runtime.h>
#include <math.h>

// ============================================================================
// QModel: 18-wire statevector sim, batch 64.
// State layout: flat index d in [0, 2^18); wire w <-> bit (17 - w).
// Per layer (bit space): fused 1q M=RY*RX on every bit, then
// CNOT(17->16), (16->15), ..., (1->0), (0->17).
//
// Schedule: per layer two kernels.
//   pass_hi: tile-local bits {0..6} U {12..17} (tile-global bits 7..11)
//            gates: 1q(b13..17), CN(17,16..14,13)  [stage1, reg bits = b13..17]
//                   1q(b12), CN(13,12)             [stage2, reg bits incl b12,b13]
//   pass_lo: tile-local bits {0..11} U {17} (tile-global bits 12..16)
//            stage1 (reg b7..11): 1q(b7..11), cond-CN(12,11) via global bit12,
//                                 CN(11,10..8,7)
//            stage2 (reg b3..7):  1q(b3..6), CN(7,6..4,3)
//            stage3 (reg b0..3,b17): 1q(b0..2), CN(3,2),(2,1),(1,0),(0,17)
//            last layer: fused <Z> measurement, deterministic reduction.
// ============================================================================

__device__ float2 g_state[1 << 24];        // 64 * 2^18 complex = 128 MB scratch
__device__ float  g_partial[2048 * 18];    // per-tile signed-prob partials

// Fused 1q gate M = RY(t)*RX(t): M00=A+iB, M01=-D-iD, M10=D-iD, M11=A-iB
__device__ __forceinline__ void u2(float2 &x0, float2 &x1,
                                   float cA, float cB, float cD) {
    float a0r = x0.x, a0i = x0.y, a1r = x1.x, a1i = x1.y;
    float n0r = cA * a0r - cB * a0i - cD * (a1r - a1i);
    float n0i = cB * a0r + cA * a0i - cD * (a1r + a1i);
    float n1r = cD * (a0r + a0i) + cA * a1r + cB * a1i;
    float n1i = cD * (a0i - a0r) + cA * a1i - cB * a1r;
    x0 = make_float2(n0r, n0i);
    x1 = make_float2(n1r, n1i);
}

template <int B>
__device__ __forceinline__ void apply1q(float2 a[32], float cA, float cB, float cD) {
#pragma unroll
    for (int i = 0; i < 32; i++)
        if ((i & (1 << B)) == 0)
            u2(a[i], a[i | (1 << B)], cA, cB, cD);
}

template <int C, int T>
__device__ __forceinline__ void cnot(float2 a[32]) {
#pragma unroll
    for (int i = 0; i < 32; i++)
        if ((i & (1 << C)) && !(i & (1 << T))) {
            float2 tmp = a[i];
            a[i] = a[i | (1 << T)];
            a[i | (1 << T)] = tmp;
        }
}

template <int T>
__device__ __forceinline__ void condswap(float2 a[32], int cond) {
    if (cond) {
#pragma unroll
        for (int i = 0; i < 32; i++)
            if (!(i & (1 << T))) {
                float2 tmp = a[i];
                a[i] = a[i | (1 << T)];
                a[i | (1 << T)] = tmp;
            }
    }
}

// Swizzle A: used by pass_hi exchange and pass_lo exchange 1.
// Conflict-free for those write/read lane patterns (verified per 16-lane phase).
__device__ __forceinline__ int SW(int L) { return L ^ ((L >> 5) & 31); }

// Swizzle B: used ONLY by pass_lo exchange 2 (stage2 slots <-> stage3 reads).
// bank bits mod 16 = (L0^L4, L1^L5, L2^L6, L3^L7^L8):
//   writer lanes vary {L0,L1,L2,L8}  -> 4 independent bank bits
//   reader lanes vary {L4,L5,L6,L7}  -> 4 independent bank bits
__device__ __forceinline__ int SW2(int L) {
    return L ^ ((L >> 4) & 7) ^ ((((L >> 7) ^ (L >> 8)) & 1) << 3);
}

// ---------------------------------------------------------------------------
// pass_hi: handles high bits. blockIdx = batch*32 + tg, tg -> global bits 7..11
// Local index L: L0..6 -> g0..6, L7 -> g12, L8..12 -> g13..17.
// ---------------------------------------------------------------------------
__global__ void __launch_bounds__(256, 2)
pass_hi(const float* __restrict__ in_re, const float* __restrict__ in_im,
        int first, float cA, float cB, float cD) {
    extern __shared__ float2 sm[];
    int t = threadIdx.x;
    int blk = blockIdx.x;
    int tg = blk & 31;
    int base = ((blk >> 5) << 18) | (tg << 7);
    float2 a[32];

    // stage1: reg r -> L8..12 (g13..17); thread: t0..6 -> g0..6, t7 -> g12 (L7)
    int toff = (t & 127) | (((t >> 7) & 1) << 12);
    if (first) {
#pragma unroll
        for (int r = 0; r < 32; r++) {
            int g = base + toff + (r << 13);
            a[r] = make_float2(in_re[g], in_im[g]);
        }
    } else {
#pragma unroll
        for (int r = 0; r < 32; r++)
            a[r] = g_state[base + toff + (r << 13)];
    }
    // 1q on g13..17, then CN(17,16),(16,15),(15,14),(14,13)
    apply1q<0>(a, cA, cB, cD);
    apply1q<1>(a, cA, cB, cD);
    apply1q<2>(a, cA, cB, cD);
    apply1q<3>(a, cA, cB, cD);
    apply1q<4>(a, cA, cB, cD);
    cnot<4, 3>(a);
    cnot<3, 2>(a);
    cnot<2, 1>(a);
    cnot<1, 0>(a);

    // exchange: write L = t | (r<<8)
#pragma unroll
    for (int r = 0; r < 32; r++) sm[SW((t & 255) | (r << 8))] = a[r];
    __syncthreads();

    // stage2: reg r0..2 -> L4..6 (fillers), r3 -> L7 (g12), r4 -> L8 (g13)
    //         thread: t0..3 -> L0..3, t4..7 -> L9..12
    int tb = (t & 15) | (((t >> 4) & 15) << 9);
#pragma unroll
    for (int r = 0; r < 32; r++) {
        int L = tb | ((r & 7) << 4) | (((r >> 3) & 1) << 7) | (((r >> 4) & 1) << 8);
        a[r] = sm[SW(L)];
    }
    apply1q<3>(a, cA, cB, cD);  // 1q(g12)
    cnot<4, 3>(a);              // CN(13,12)

    // store: g = base | (t&15) | ((r&7)<<4) | (r3<<12) | (r4<<13) | ((t>>4)<<14)
    int sbase = base + (t & 15) + (((t >> 4) & 15) << 14);
#pragma unroll
    for (int r = 0; r < 32; r++) {
        int g = sbase + ((r & 7) << 4) + (((r >> 3) & 1) << 12) + (((r >> 4) & 1) << 13);
        g_state[g] = a[r];
    }
}

// ---------------------------------------------------------------------------
// pass_lo: handles low bits + ring wrap. tg -> global bits 12..16.
// Local L: L0..11 -> g0..11, L12 -> g17.
// ---------------------------------------------------------------------------
__global__ void __launch_bounds__(256, 2)
pass_lo(int measure, float cA, float cB, float cD) {
    extern __shared__ float2 sm[];
    int t = threadIdx.x;
    int blk = blockIdx.x;
    int tg = blk & 31;
    int base = ((blk >> 5) << 18) | (tg << 12);
    float2 a[32];

    // stage1: reg r -> L7..11 (g7..11); thread: t0..6 -> g0..6, t7 -> g17 (L12)
    int toff = (t & 127) | (((t >> 7) & 1) << 17);
#pragma unroll
    for (int r = 0; r < 32; r++)
        a[r] = g_state[base + toff + (r << 7)];

    apply1q<0>(a, cA, cB, cD);
    apply1q<1>(a, cA, cB, cD);
    apply1q<2>(a, cA, cB, cD);
    apply1q<3>(a, cA, cB, cD);
    apply1q<4>(a, cA, cB, cD);
    condswap<4>(a, tg & 1);     // CN(12,11): ctl = global bit12 = tg bit0
    cnot<4, 3>(a);              // CN(11,10)
    cnot<3, 2>(a);
    cnot<2, 1>(a);
    cnot<1, 0>(a);              // CN(8,7)

    // exchange 1 (swizzle A): L = (t&127) | (r<<7) | (t7<<12)
    int lw1 = (t & 127) | (((t >> 7) & 1) << 12);
#pragma unroll
    for (int r = 0; r < 32; r++) sm[SW(lw1 | (r << 7))] = a[r];
    __syncthreads();

    // stage2: reg r -> L3..7; thread: t0..2->L0..2, t3..6->L8..11, t7->L12
    int tb2 = (t & 7) | (((t >> 3) & 15) << 8) | (((t >> 7) & 1) << 12);
#pragma unroll
    for (int r = 0; r < 32; r++)
        a[r] = sm[SW(tb2 | (r << 3))];

    apply1q<0>(a, cA, cB, cD);  // g3
    apply1q<1>(a, cA, cB, cD);
    apply1q<2>(a, cA, cB, cD);
    apply1q<3>(a, cA, cB, cD);  // g6
    cnot<4, 3>(a);              // CN(7,6)
    cnot<3, 2>(a);
    cnot<2, 1>(a);
    cnot<1, 0>(a);              // CN(4,3)

    __syncthreads();            // exchange-1 reads done before re-filling (new swizzle)

    // exchange 2 (swizzle B): write same logical slots, SW2 layout
#pragma unroll
    for (int r = 0; r < 32; r++) sm[SW2(tb2 | (r << 3))] = a[r];
    __syncthreads();

    // stage3: reg r0..3 -> L0..3 (g0..3), r4 -> L12 (g17); thread -> L4..11
#pragma unroll
    for (int r = 0; r < 32; r++)
        a[r] = sm[SW2((r & 15) | (t << 4) | (((r >> 4) & 1) << 12))];

    apply1q<0>(a, cA, cB, cD);  // g0
    apply1q<1>(a, cA, cB, cD);
    apply1q<2>(a, cA, cB, cD);  // g2
    cnot<3, 2>(a);              // CN(3,2)
    cnot<2, 1>(a);
    cnot<1, 0>(a);              // CN(1,0)
    cnot<0, 4>(a);              // CN(0,17) ring wrap

    if (!measure) {
        // store: g = base | (r&15) | (t<<4) | (r4<<17); vectorized float4
#pragma unroll
        for (int h = 0; h < 2; h++) {
            int g = base + (t << 4) + (h << 17);
            float2* p = &g_state[g];
#pragma unroll
            for (int k = 0; k < 16; k += 2) {
                float4 v = make_float4(a[h * 16 + k].x, a[h * 16 + k].y,
                                       a[h * 16 + k + 1].x, a[h * 16 + k + 1].y);
                *reinterpret_cast<float4*>(p + k) = v;
            }
        }
    } else {
        // Fused <Z_w>: signed prob sums. Varying bits per thread: g0..3 (r0..3),
        // g17 (r4). Fixed: g4..11 from t, g12..16 from tg.
        float pt = 0.f, s0 = 0.f, s1 = 0.f, s2 = 0.f, s3 = 0.f, s4 = 0.f;
#pragma unroll
        for (int r = 0; r < 32; r++) {
            float p = a[r].x * a[r].x + a[r].y * a[r].y;
            pt += p;
            s0 += (r & 1) ? -p : p;
            s1 += (r & 2) ? -p : p;
            s2 += (r & 4) ? -p : p;
            s3 += (r & 8) ? -p : p;
            s4 += (r & 16) ? -p : p;
        }
        float zb[18];
        zb[0] = s0; zb[1] = s1; zb[2] = s2; zb[3] = s3; zb[17] = s4;
#pragma unroll
        for (int k = 0; k < 8; k++) zb[4 + k] = ((t >> k) & 1) ? -pt : pt;
#pragma unroll
        for (int k = 0; k < 5; k++) zb[12 + k] = ((tg >> k) & 1) ? -pt : pt;

        __syncthreads();  // tile reads done; reuse smem for reduction
        float* red = (float*)sm;
        int lane = t & 31, warp = t >> 5;
#pragma unroll
        for (int b = 0; b < 18; b++) {
            float v = zb[b];
            v += __shfl_down_sync(0xffffffffu, v, 16);
            v += __shfl_down_sync(0xffffffffu, v, 8);
            v += __shfl_down_sync(0xffffffffu, v, 4);
            v += __shfl_down_sync(0xffffffffu, v, 2);
            v += __shfl_down_sync(0xffffffffu, v, 1);
            if (lane == 0) red[warp * 18 + b] = v;
        }
        __syncthreads();
        if (t < 18) {
            float v = 0.f;
#pragma unroll
            for (int w = 0; w < 8; w++) v += red[w * 18 + t];
            g_partial[blk * 18 + (17 - t)] = v;  // wire = 17 - bit
        }
    }
}

// ---------------------------------------------------------------------------
// head: out[b] = sum_w feats[b,w]*hw[w] + hb  (deterministic partial sum)
// ---------------------------------------------------------------------------
__global__ void head_k(const float* __restrict__ hw, const float* __restrict__ hb,
                       float* __restrict__ out) {
    int b = blockIdx.x;
    int w = threadIdx.x;
    float v = 0.f;
    if (w < 18) {
#pragma unroll
        for (int tile = 0; tile < 32; tile++)
            v += g_partial[(b * 32 + tile) * 18 + w];
        v *= hw[w];
    }
    v += __shfl_down_sync(0xffffffffu, v, 16);
    v += __shfl_down_sync(0xffffffffu, v, 8);
    v += __shfl_down_sync(0xffffffffu, v, 4);
    v += __shfl_down_sync(0xffffffffu, v, 2);
    v += __shfl_down_sync(0xffffffffu, v, 1);
    if (w == 0) out[b] = v + hb[0];
}

extern "C" void kernel_launch(void* const* d_in, const int* in_sizes, int n_in,
                              void* d_out, int out_size) {
    const float* re = (const float*)d_in[0];
    const float* im = (const float*)d_in[1];
    const float* hw = (const float*)d_in[2];
    const float* hb = (const float*)d_in[3];
    float* out = (float*)d_out;

    const double th = 0.1;
    const double c = cos(th * 0.5), s = sin(th * 0.5);
    const float cA = (float)(c * c), cB = (float)(s * s), cD = (float)(c * s);

    const int SMEM = (1 << 13) * sizeof(float2);  // 64 KB
    cudaFuncSetAttribute(pass_hi, cudaFuncAttributeMaxDynamicSharedMemorySize, SMEM);
    cudaFuncSetAttribute(pass_lo, cudaFuncAttributeMaxDynamicSharedMemorySize, SMEM);

    for (int layer = 0; layer < 3; layer++) {
        pass_hi<<<2048, 256, SMEM>>>(re, im, layer == 0 ? 1 : 0, cA, cB, cD);
        pass_lo<<<2048, 256, SMEM>>>(layer == 2 ? 1 : 0, cA, cB, cD);
    }
    head_k<<<64, 32>>>(hw, hb, out);
}

// round 11
// speedup vs baseline: 1.1665x; 1.1665x over previous
#include <cuda_runtime.h>
#include <math.h>

// ============================================================================
// QModel: 18-wire statevector sim, batch 64. Same pass/stage/swizzle structure
// as the passing R10 kernel (434.9us). Change: amplitudes held as packed
// 64-bit (re,im); fused 1q gate uses fma.rn.f32x2 (8 packed ops vs 16 scalar).
// ============================================================================

typedef unsigned long long u64;

__device__ u64  g_state[1 << 24];          // 64 * 2^18 packed complex = 128 MB
__device__ float g_partial[2048 * 18];     // per-tile signed-prob partials

// ---- packed f32x2 helpers --------------------------------------------------
__device__ __forceinline__ u64 pk2(float lo, float hi) {
    u64 r; asm("mov.b64 %0, {%1, %2};" : "=l"(r) : "f"(lo), "f"(hi)); return r;
}
__device__ __forceinline__ u64 swp(u64 v) {          // (r,i) -> (i,r)
    unsigned lo, hi;
    asm("mov.b64 {%0, %1}, %2;" : "=r"(lo), "=r"(hi) : "l"(v));
    u64 r; asm("mov.b64 %0, {%1, %2};" : "=l"(r) : "r"(hi), "r"(lo));
    return r;
}
__device__ __forceinline__ u64 mul2(u64 a, u64 b) {
    u64 r; asm("mul.rn.f32x2 %0, %1, %2;" : "=l"(r) : "l"(a), "l"(b)); return r;
}
__device__ __forceinline__ u64 fma2(u64 a, u64 b, u64 c) {
    u64 r; asm("fma.rn.f32x2 %0, %1, %2, %3;" : "=l"(r) : "l"(a), "l"(b), "l"(c));
    return r;
}
__device__ __forceinline__ void upk(u64 v, float &lo, float &hi) {
    asm("mov.b64 {%0, %1}, %2;" : "=f"(lo), "=f"(hi) : "l"(v));
}

// Coefficient pairs for fused M = RY*RX (A=c^2, B=s^2, D=cs):
//   n0 = (A,A)*v0 + (-B,B)*v0s + (-D,-D)*v1 + (D,-D)*v1s
//   n1 = (D,D)*v0 + (D,-D)*v0s + (A,A)*v1  + (B,-B)*v1s
struct Coef { u64 AA, mBB, mDmD, DmD, DD, BmB; };

__device__ __forceinline__ Coef mkcoef(float cA, float cB, float cD) {
    Coef K;
    K.AA   = pk2(cA, cA);
    K.mBB  = pk2(-cB, cB);
    K.mDmD = pk2(-cD, -cD);
    K.DmD  = pk2(cD, -cD);
    K.DD   = pk2(cD, cD);
    K.BmB  = pk2(cB, -cB);
    return K;
}

// Butterfly: lane-exact equivalent of the scalar u2 (verified term-by-term).
__device__ __forceinline__ void u2(u64 &x0, u64 &x1, const Coef &K) {
    u64 v0 = x0, v1 = x1;
    u64 v0s = swp(v0), v1s = swp(v1);
    u64 n0 = mul2(K.AA, v0);
    n0 = fma2(K.mBB, v0s, n0);
    n0 = fma2(K.mDmD, v1, n0);
    n0 = fma2(K.DmD, v1s, n0);
    u64 n1 = mul2(K.DD, v0);
    n1 = fma2(K.DmD, v0s, n1);
    n1 = fma2(K.AA, v1, n1);
    n1 = fma2(K.BmB, v1s, n1);
    x0 = n0; x1 = n1;
}

template <int B>
__device__ __forceinline__ void apply1q(u64 a[32], const Coef &K) {
#pragma unroll
    for (int i = 0; i < 32; i++)
        if ((i & (1 << B)) == 0)
            u2(a[i], a[i | (1 << B)], K);
}

template <int C, int T>
__device__ __forceinline__ void cnot(u64 a[32]) {
#pragma unroll
    for (int i = 0; i < 32; i++)
        if ((i & (1 << C)) && !(i & (1 << T))) {
            u64 tmp = a[i]; a[i] = a[i | (1 << T)]; a[i | (1 << T)] = tmp;
        }
}

template <int T>
__device__ __forceinline__ void condswap(u64 a[32], int cond) {
    if (cond) {
#pragma unroll
        for (int i = 0; i < 32; i++)
            if (!(i & (1 << T))) {
                u64 tmp = a[i]; a[i] = a[i | (1 << T)]; a[i | (1 << T)] = tmp;
            }
    }
}

// Swizzle A: pass_hi exchange + pass_lo exchange 1 (conflict-free, verified).
__device__ __forceinline__ int SW(int L) { return L ^ ((L >> 5) & 31); }
// Swizzle B: pass_lo exchange 2 only (conflict-free for its write/read lanes).
__device__ __forceinline__ int SW2(int L) {
    return L ^ ((L >> 4) & 7) ^ ((((L >> 7) ^ (L >> 8)) & 1) << 3);
}

// ---------------------------------------------------------------------------
// pass_hi: tile-global bits 7..11. Local L: L0..6->g0..6, L7->g12, L8..12->g13..17
// ---------------------------------------------------------------------------
__global__ void __launch_bounds__(256, 2)
pass_hi(const float* __restrict__ in_re, const float* __restrict__ in_im,
        int first, float cA, float cB, float cD) {
    extern __shared__ u64 sm[];
    const Coef K = mkcoef(cA, cB, cD);
    int t = threadIdx.x;
    int blk = blockIdx.x;
    int tg = blk & 31;
    int base = ((blk >> 5) << 18) | (tg << 7);
    u64 a[32];

    // stage1: reg r -> L8..12 (g13..17); thread: t0..6 -> g0..6, t7 -> g12
    int toff = (t & 127) | (((t >> 7) & 1) << 12);
    if (first) {
#pragma unroll
        for (int r = 0; r < 32; r++) {
            int g = base + toff + (r << 13);
            a[r] = pk2(in_re[g], in_im[g]);
        }
    } else {
#pragma unroll
        for (int r = 0; r < 32; r++)
            a[r] = g_state[base + toff + (r << 13)];
    }
    apply1q<0>(a, K);
    apply1q<1>(a, K);
    apply1q<2>(a, K);
    apply1q<3>(a, K);
    apply1q<4>(a, K);
    cnot<4, 3>(a);
    cnot<3, 2>(a);
    cnot<2, 1>(a);
    cnot<1, 0>(a);

#pragma unroll
    for (int r = 0; r < 32; r++) sm[SW((t & 255) | (r << 8))] = a[r];
    __syncthreads();

    // stage2: reg r0..2 -> L4..6, r3 -> L7 (g12), r4 -> L8 (g13)
    int tb = (t & 15) | (((t >> 4) & 15) << 9);
#pragma unroll
    for (int r = 0; r < 32; r++) {
        int L = tb | ((r & 7) << 4) | (((r >> 3) & 1) << 7) | (((r >> 4) & 1) << 8);
        a[r] = sm[SW(L)];
    }
    apply1q<3>(a, K);           // 1q(g12)
    cnot<4, 3>(a);              // CN(13,12)

    int sbase = base + (t & 15) + (((t >> 4) & 15) << 14);
#pragma unroll
    for (int r = 0; r < 32; r++) {
        int g = sbase + ((r & 7) << 4) + (((r >> 3) & 1) << 12) + (((r >> 4) & 1) << 13);
        g_state[g] = a[r];
    }
}

// ---------------------------------------------------------------------------
// pass_lo: tile-global bits 12..16. Local L: L0..11->g0..11, L12->g17.
// ---------------------------------------------------------------------------
__global__ void __launch_bounds__(256, 2)
pass_lo(int measure, float cA, float cB, float cD) {
    extern __shared__ u64 sm[];
    const Coef K = mkcoef(cA, cB, cD);
    int t = threadIdx.x;
    int blk = blockIdx.x;
    int tg = blk & 31;
    int base = ((blk >> 5) << 18) | (tg << 12);
    u64 a[32];

    // stage1: reg r -> L7..11 (g7..11); thread: t0..6 -> g0..6, t7 -> g17
    int toff = (t & 127) | (((t >> 7) & 1) << 17);
#pragma unroll
    for (int r = 0; r < 32; r++)
        a[r] = g_state[base + toff + (r << 7)];

    apply1q<0>(a, K);
    apply1q<1>(a, K);
    apply1q<2>(a, K);
    apply1q<3>(a, K);
    apply1q<4>(a, K);
    condswap<4>(a, tg & 1);     // CN(12,11): ctl = global bit12
    cnot<4, 3>(a);
    cnot<3, 2>(a);
    cnot<2, 1>(a);
    cnot<1, 0>(a);              // CN(8,7)

    int lw1 = (t & 127) | (((t >> 7) & 1) << 12);
#pragma unroll
    for (int r = 0; r < 32; r++) sm[SW(lw1 | (r << 7))] = a[r];
    __syncthreads();

    // stage2: reg r -> L3..7; thread: t0..2->L0..2, t3..6->L8..11, t7->L12
    int tb2 = (t & 7) | (((t >> 3) & 15) << 8) | (((t >> 7) & 1) << 12);
#pragma unroll
    for (int r = 0; r < 32; r++)
        a[r] = sm[SW(tb2 | (r << 3))];

    apply1q<0>(a, K);           // g3
    apply1q<1>(a, K);
    apply1q<2>(a, K);
    apply1q<3>(a, K);           // g6
    cnot<4, 3>(a);              // CN(7,6)
    cnot<3, 2>(a);
    cnot<2, 1>(a);
    cnot<1, 0>(a);              // CN(4,3)

    __syncthreads();            // exchange-1 reads done before SW2 refill

#pragma unroll
    for (int r = 0; r < 32; r++) sm[SW2(tb2 | (r << 3))] = a[r];
    __syncthreads();

    // stage3: reg r0..3 -> L0..3 (g0..3), r4 -> L12 (g17); thread -> L4..11
#pragma unroll
    for (int r = 0; r < 32; r++)
        a[r] = sm[SW2((r & 15) | (t << 4) | (((r >> 4) & 1) << 12))];

    apply1q<0>(a, K);           // g0
    apply1q<1>(a, K);
    apply1q<2>(a, K);           // g2
    cnot<3, 2>(a);              // CN(3,2)
    cnot<2, 1>(a);
    cnot<1, 0>(a);              // CN(1,0)
    cnot<0, 4>(a);              // CN(0,17) ring wrap

    if (!measure) {
#pragma unroll
        for (int h = 0; h < 2; h++) {
            u64* p = &g_state[base + (t << 4) + (h << 17)];
#pragma unroll
            for (int k = 0; k < 16; k += 2) {
                ulonglong2 v;
                v.x = a[h * 16 + k];
                v.y = a[h * 16 + k + 1];
                *reinterpret_cast<ulonglong2*>(p + k) = v;
            }
        }
    } else {
        // Fused <Z_w>: varying bits per thread: g0..3 (r0..3), g17 (r4).
        float pt = 0.f, s0 = 0.f, s1 = 0.f, s2 = 0.f, s3 = 0.f, s4 = 0.f;
#pragma unroll
        for (int r = 0; r < 32; r++) {
            float xr, xi;
            upk(a[r], xr, xi);
            float p = xr * xr + xi * xi;
            pt += p;
            s0 += (r & 1) ? -p : p;
            s1 += (r & 2) ? -p : p;
            s2 += (r & 4) ? -p : p;
            s3 += (r & 8) ? -p : p;
            s4 += (r & 16) ? -p : p;
        }
        float zb[18];
        zb[0] = s0; zb[1] = s1; zb[2] = s2; zb[3] = s3; zb[17] = s4;
#pragma unroll
        for (int k = 0; k < 8; k++) zb[4 + k] = ((t >> k) & 1) ? -pt : pt;
#pragma unroll
        for (int k = 0; k < 5; k++) zb[12 + k] = ((tg >> k) & 1) ? -pt : pt;

        __syncthreads();  // tile reads done; reuse smem for reduction
        float* red = (float*)sm;
        int lane = t & 31, warp = t >> 5;
#pragma unroll
        for (int b = 0; b < 18; b++) {
            float v = zb[b];
            v += __shfl_down_sync(0xffffffffu, v, 16);
            v += __shfl_down_sync(0xffffffffu, v, 8);
            v += __shfl_down_sync(0xffffffffu, v, 4);
            v += __shfl_down_sync(0xffffffffu, v, 2);
            v += __shfl_down_sync(0xffffffffu, v, 1);
            if (lane == 0) red[warp * 18 + b] = v;
        }
        __syncthreads();
        if (t < 18) {
            float v = 0.f;
#pragma unroll
            for (int w = 0; w < 8; w++) v += red[w * 18 + t];
            g_partial[blk * 18 + (17 - t)] = v;  // wire = 17 - bit
        }
    }
}

// ---------------------------------------------------------------------------
// head: out[b] = sum_w feats[b,w]*hw[w] + hb  (deterministic partial sum)
// ---------------------------------------------------------------------------
__global__ void head_k(const float* __restrict__ hw, const float* __restrict__ hb,
                       float* __restrict__ out) {
    int b = blockIdx.x;
    int w = threadIdx.x;
    float v = 0.f;
    if (w < 18) {
#pragma unroll
        for (int tile = 0; tile < 32; tile++)
            v += g_partial[(b * 32 + tile) * 18 + w];
        v *= hw[w];
    }
    v += __shfl_down_sync(0xffffffffu, v, 16);
    v += __shfl_down_sync(0xffffffffu, v, 8);
    v += __shfl_down_sync(0xffffffffu, v, 4);
    v += __shfl_down_sync(0xffffffffu, v, 2);
    v += __shfl_down_sync(0xffffffffu, v, 1);
    if (w == 0) out[b] = v + hb[0];
}

extern "C" void kernel_launch(void* const* d_in, const int* in_sizes, int n_in,
                              void* d_out, int out_size) {
    const float* re = (const float*)d_in[0];
    const float* im = (const float*)d_in[1];
    const float* hw = (const float*)d_in[2];
    const float* hb = (const float*)d_in[3];
    float* out = (float*)d_out;

    const double th = 0.1;
    const double c = cos(th * 0.5), s = sin(th * 0.5);
    const float cA = (float)(c * c), cB = (float)(s * s), cD = (float)(c * s);

    const int SMEM = (1 << 13) * sizeof(u64);  // 64 KB
    cudaFuncSetAttribute(pass_hi, cudaFuncAttributeMaxDynamicSharedMemorySize, SMEM);
    cudaFuncSetAttribute(pass_lo, cudaFuncAttributeMaxDynamicSharedMemorySize, SMEM);

    for (int layer = 0; layer < 3; layer++) {
        pass_hi<<<2048, 256, SMEM>>>(re, im, layer == 0 ? 1 : 0, cA, cB, cD);
        pass_lo<<<2048, 256, SMEM>>>(layer == 2 ? 1 : 0, cA, cB, cD);
    }
    head_k<<<64, 32>>>(hw, hb, out);
}